// round 3
// baseline (speedup 1.0000x reference)
#include <cuda_runtime.h>
#include <cuda_bf16.h>
#include <math.h>

#define NN 16384
#define DD 64

// Scratch (static __device__ — allocation is forbidden). Kernels reference
// these by symbol; kernel_launch performs ONLY kernel launches.
__device__ __align__(16) float g_h1[NN * DD];    // z @ W
__device__ __align__(16) float g_h2[NN * DD];    // GCN output (pre-relu)
__device__ float g_deg[NN];
__device__ float g_dinv[NN];
__device__ int   g_is64;                         // edge_index dtype flag

// ---------------- dtype probe ----------------
// View edge buffer as u32 words. If ALL odd words among the first 2E words are
// zero -> values are int64 (high halves of ids < 16384). Otherwise int32.
__global__ void detect_init_kernel() {
    if (threadIdx.x == 0 && blockIdx.x == 0) g_is64 = 1;
}
__global__ void detect_kernel(const unsigned* __restrict__ ei32, int E) {
    int i = blockIdx.x * 256 + threadIdx.x;      // over E pairs
    if (i < E && ei32[2 * i + 1] != 0u) g_is64 = 0;  // racy all-write-0: fine
}

__device__ __forceinline__ int edge_get(const void* ei, int is64, size_t idx) {
    if (is64) return (int)((const long long*)ei)[idx];
    return ((const int*)ei)[idx];
}

// ---------------- Kernel: h1 = z @ W ----------------
__global__ void linear_kernel(const float* __restrict__ z,
                              const float* __restrict__ W) {
    __shared__ float Ws[DD * DD];
    __shared__ float zs[4 * DD];
    int tid = threadIdx.x;                 // 256 threads
    int j = tid & 63;
    int rl = tid >> 6;                     // 0..3
    for (int i = tid; i < DD * DD; i += 256) Ws[i] = W[i];
    zs[tid] = z[(size_t)blockIdx.x * 256 + tid];
    __syncthreads();
    float s = 0.0f;
#pragma unroll
    for (int k = 0; k < DD; k++) s = fmaf(zs[rl * DD + k], Ws[k * DD + j], s);
    g_h1[(size_t)blockIdx.x * 256 + tid] = s;
}

// ---------------- deg init (self-loop = 1) ----------------
__global__ void deg_init_kernel() {
    int i = blockIdx.x * 256 + threadIdx.x;
    if (i < NN) g_deg[i] = 1.0f;
}

// ---------------- deg count over cols ----------------
__global__ void deg_count_kernel(const void* __restrict__ ei, int E) {
    int e = blockIdx.x * 256 + threadIdx.x;
    if (e >= E) return;
    int is64 = g_is64;
    int c = edge_get(ei, is64, (size_t)E + e);
    if ((unsigned)c < NN) atomicAdd(&g_deg[c], 1.0f);
}

// ---------------- dinv = 1/sqrt(deg) ----------------
__global__ void dinv_kernel() {
    int i = blockIdx.x * 256 + threadIdx.x;
    if (i < NN) g_dinv[i] = 1.0f / sqrtf(g_deg[i]);
}

// ---------------- h2 = h1*dinv^2 + b (self-loop + bias) ----------------
__global__ void init_out_kernel(const float* __restrict__ b) {
    int i = blockIdx.x * 256 + threadIdx.x;   // over NN*DD
    int node = i >> 6;
    int j = i & 63;
    float di = g_dinv[node];
    g_h2[i] = g_h1[i] * di * di + b[j];
}

// ---------------- edge scatter: h2[col] += h1[row]*norm ----------------
__global__ void scatter_kernel(const void* __restrict__ ei, int E) {
    int t = blockIdx.x * 256 + threadIdx.x;  // over E*16
    int e = t >> 4;
    int q = t & 15;
    if (e >= E) return;
    int is64 = g_is64;
    int r = edge_get(ei, is64, (size_t)e);
    int c = edge_get(ei, is64, (size_t)E + e);
    if ((unsigned)r >= NN || (unsigned)c >= NN) return;
    float norm = g_dinv[r] * g_dinv[c];
    const float4 v = *(const float4*)&g_h1[((size_t)r << 6) + q * 4];
    float* dst = &g_h2[((size_t)c << 6) + q * 4];
    atomicAdd(dst + 0, v.x * norm);
    atomicAdd(dst + 1, v.y * norm);
    atomicAdd(dst + 2, v.z * norm);
    atomicAdd(dst + 3, v.w * norm);
}

// ---------------- A = relu(h2) @ relu(h2)^T (symmetric) ----------------
// 128x128 tile, K chunked 2x32, 256 threads, 8x8 register blocking.
// Static smem (<48KB). Lower-triangular blocks only; mirror from registers.
#define SB 132   // BsT stride (padded, 16B-aligned for float4 LDS)

__global__ void __launch_bounds__(256) gemm_ht_kernel(float* __restrict__ C, int n) {
    int bx = blockIdx.x, by = blockIdx.y;
    if (bx > by) return;

    __shared__ float As[128 * 32];   // natural [row][k], 16 KB
    __shared__ float Bs[32 * SB];    // transposed [k][col], 16.5 KB

    int tid = threadIdx.x;          // 256
    int tx = tid & 15;
    int ty = tid >> 4;

    const float4* H4 = (const float4*)g_h2;

    float acc[8][8];
#pragma unroll
    for (int i = 0; i < 8; i++)
#pragma unroll
        for (int j = 0; j < 8; j++) acc[i][j] = 0.0f;

#pragma unroll
    for (int kc = 0; kc < 2; kc++) {
#pragma unroll
        for (int i = 0; i < 4; i++) {
            int idx = i * 256 + tid;
            int row = idx >> 3, kq = idx & 7;
            float4 v = H4[(size_t)(by * 128 + row) * 16 + kc * 8 + kq];
            v.x = fmaxf(v.x, 0.f); v.y = fmaxf(v.y, 0.f);
            v.z = fmaxf(v.z, 0.f); v.w = fmaxf(v.w, 0.f);
            *(float4*)&As[row * 32 + kq * 4] = v;
        }
#pragma unroll
        for (int i = 0; i < 4; i++) {
            int idx = i * 256 + tid;
            int col = idx >> 3, kq = idx & 7;
            float4 v = H4[(size_t)(bx * 128 + col) * 16 + kc * 8 + kq];
            v.x = fmaxf(v.x, 0.f); v.y = fmaxf(v.y, 0.f);
            v.z = fmaxf(v.z, 0.f); v.w = fmaxf(v.w, 0.f);
            Bs[(4 * kq + 0) * SB + col] = v.x;
            Bs[(4 * kq + 1) * SB + col] = v.y;
            Bs[(4 * kq + 2) * SB + col] = v.z;
            Bs[(4 * kq + 3) * SB + col] = v.w;
        }
        __syncthreads();

#pragma unroll 8
        for (int k = 0; k < 32; k++) {
            float a[8], b[8];
#pragma unroll
            for (int i = 0; i < 8; i++) a[i] = As[(ty * 8 + i) * 32 + k];
            float4 b0 = *(const float4*)&Bs[k * SB + tx * 8];
            float4 b1 = *(const float4*)&Bs[k * SB + tx * 8 + 4];
            b[0] = b0.x; b[1] = b0.y; b[2] = b0.z; b[3] = b0.w;
            b[4] = b1.x; b[5] = b1.y; b[6] = b1.z; b[7] = b1.w;
#pragma unroll
            for (int i = 0; i < 8; i++)
#pragma unroll
                for (int j = 0; j < 8; j++)
                    acc[i][j] = fmaf(a[i], b[j], acc[i][j]);
        }
        __syncthreads();
    }

    // Lower tile: rows by*128+ty*8+i, cols bx*128+tx*8..
#pragma unroll
    for (int i = 0; i < 8; i++) {
        size_t r = (size_t)(by * 128 + ty * 8 + i);
        size_t cb = (size_t)(bx * 128 + tx * 8);
        float4 v0 = make_float4(acc[i][0], acc[i][1], acc[i][2], acc[i][3]);
        float4 v1 = make_float4(acc[i][4], acc[i][5], acc[i][6], acc[i][7]);
        *(float4*)&C[r * (size_t)n + cb] = v0;
        *(float4*)&C[r * (size_t)n + cb + 4] = v1;
    }

    // Mirror tile (transpose) from registers
    if (bx != by) {
#pragma unroll
        for (int j = 0; j < 8; j++) {
            size_t r = (size_t)(bx * 128 + tx * 8 + j);
            size_t cb = (size_t)(by * 128 + ty * 8);
            float4 v0 = make_float4(acc[0][j], acc[1][j], acc[2][j], acc[3][j]);
            float4 v1 = make_float4(acc[4][j], acc[5][j], acc[6][j], acc[7][j]);
            *(float4*)&C[r * (size_t)n + cb] = v0;
            *(float4*)&C[r * (size_t)n + cb + 4] = v1;
        }
    }
}

// ---------------- Launcher (kernel launches ONLY) ----------------
extern "C" void kernel_launch(void* const* d_in, const int* in_sizes, int n_in,
                              void* d_out, int out_size) {
    const float* z  = (const float*)d_in[0];
    const void*  ei = d_in[1];              // int32 or int64 — probed on device
    const float* W  = (const float*)d_in[2];
    const float* b  = (const float*)d_in[3];
    float* out = (float*)d_out;

    int n = in_sizes[0] / DD;        // 16384
    int E = in_sizes[1] / 2;         // 524288

    // dtype probe (safe under both dtypes: reads only 2E u32 words)
    detect_init_kernel<<<1, 32>>>();
    detect_kernel<<<(E + 255) / 256, 256>>>((const unsigned*)ei, E);

    // GCN conv
    linear_kernel<<<n * DD / 256, 256>>>(z, W);
    deg_init_kernel<<<(n + 255) / 256, 256>>>();
    deg_count_kernel<<<(E + 255) / 256, 256>>>(ei, E);
    dinv_kernel<<<(n + 255) / 256, 256>>>();
    init_out_kernel<<<n * DD / 256, 256>>>(b);
    scatter_kernel<<<(E * 16 + 255) / 256, 256>>>(ei, E);

    // A_hat = relu(h2) @ relu(h2)^T  (symmetric: lower-tri blocks + mirror)
    dim3 grid(n / 128, n / 128);
    gemm_ht_kernel<<<grid, 256>>>(out, n);
}

// round 4
// speedup vs baseline: 2.4141x; 2.4141x over previous
#include <cuda_runtime.h>
#include <cuda_bf16.h>
#include <math.h>
#include <stdint.h>

#define NN 16384
#define DD 64

// Scratch (static __device__ — allocation is forbidden).
__device__ __align__(16) float g_h1[NN * DD];    // z @ W
__device__ __align__(16) float g_h2[NN * DD];    // GCN output (pre-relu)
__device__ float g_deg[NN];
__device__ float g_dinv[NN];
__device__ int   g_is64;                         // edge_index dtype flag

// ---------------- dtype probe ----------------
__global__ void detect_init_kernel() {
    if (threadIdx.x == 0 && blockIdx.x == 0) g_is64 = 1;
}
__global__ void detect_kernel(const unsigned* __restrict__ ei32, int E) {
    int i = blockIdx.x * 256 + threadIdx.x;      // over E pairs
    if (i < E && ei32[2 * i + 1] != 0u) g_is64 = 0;
}
__device__ __forceinline__ int edge_get(const void* ei, int is64, size_t idx) {
    if (is64) return (int)((const long long*)ei)[idx];
    return ((const int*)ei)[idx];
}

// ---------------- h1 = z @ W ----------------
__global__ void linear_kernel(const float* __restrict__ z,
                              const float* __restrict__ W) {
    __shared__ float Ws[DD * DD];
    __shared__ float zs[4 * DD];
    int tid = threadIdx.x;                 // 256 threads
    int j = tid & 63;
    int rl = tid >> 6;
    for (int i = tid; i < DD * DD; i += 256) Ws[i] = W[i];
    zs[tid] = z[(size_t)blockIdx.x * 256 + tid];
    __syncthreads();
    float s = 0.0f;
#pragma unroll
    for (int k = 0; k < DD; k++) s = fmaf(zs[rl * DD + k], Ws[k * DD + j], s);
    g_h1[(size_t)blockIdx.x * 256 + tid] = s;
}

// ---------------- deg init (self-loop = 1) ----------------
__global__ void deg_init_kernel() {
    int i = blockIdx.x * 256 + threadIdx.x;
    if (i < NN) g_deg[i] = 1.0f;
}
// ---------------- deg count over cols ----------------
__global__ void deg_count_kernel(const void* __restrict__ ei, int E) {
    int e = blockIdx.x * 256 + threadIdx.x;
    if (e >= E) return;
    int c = edge_get(ei, g_is64, (size_t)E + e);
    if ((unsigned)c < NN) atomicAdd(&g_deg[c], 1.0f);
}
// ---------------- dinv = 1/sqrt(deg) ----------------
__global__ void dinv_kernel() {
    int i = blockIdx.x * 256 + threadIdx.x;
    if (i < NN) g_dinv[i] = 1.0f / sqrtf(g_deg[i]);
}
// ---------------- h2 = h1*dinv^2 + b ----------------
__global__ void init_out_kernel(const float* __restrict__ b) {
    int i = blockIdx.x * 256 + threadIdx.x;   // over NN*DD
    int node = i >> 6;
    int j = i & 63;
    float di = g_dinv[node];
    g_h2[i] = g_h1[i] * di * di + b[j];
}

// ---------------- edge scatter: h2[col] += h1[row]*norm (vector RED) ----------------
__global__ void scatter_kernel(const void* __restrict__ ei, int E) {
    int t = blockIdx.x * 256 + threadIdx.x;  // over E*16
    int e = t >> 4;
    int q = t & 15;
    if (e >= E) return;
    int is64 = g_is64;
    int r = edge_get(ei, is64, (size_t)e);
    int c = edge_get(ei, is64, (size_t)E + e);
    if ((unsigned)r >= NN || (unsigned)c >= NN) return;
    float norm = g_dinv[r] * g_dinv[c];
    const float4 v = *(const float4*)&g_h1[((size_t)r << 6) + q * 4];
    float* dst = &g_h2[((size_t)c << 6) + q * 4];
    asm volatile("red.global.add.v4.f32 [%0], {%1,%2,%3,%4};"
                 :: "l"(dst), "f"(v.x * norm), "f"(v.y * norm),
                    "f"(v.z * norm), "f"(v.w * norm)
                 : "memory");
}

// ---------------- A = relu(h2) @ relu(h2)^T via mma.sync tf32 ----------------
// 128x128 block tile, 8 warps in 4(M)x2(N), warp tile 32x64.
// Both As and Bs in natural [node][k] layout, stride 36 u32 -> every fragment
// LDS and the uint4 STS are bank-conflict-free.
// Lower-triangular blocks only; mirror tile written from registers.
#define SAK 36

__device__ __forceinline__ uint32_t f2tf32(float x) {
    uint32_t r;
    asm("cvt.rna.tf32.f32 %0, %1;" : "=r"(r) : "f"(x));
    return r;
}

__device__ __forceinline__ void mma_tf32(float* d, const uint32_t* a, const uint32_t* b) {
    asm("mma.sync.aligned.m16n8k8.row.col.f32.tf32.tf32.f32 "
        "{%0,%1,%2,%3}, {%4,%5,%6,%7}, {%8,%9}, {%0,%1,%2,%3};"
        : "+f"(d[0]), "+f"(d[1]), "+f"(d[2]), "+f"(d[3])
        : "r"(a[0]), "r"(a[1]), "r"(a[2]), "r"(a[3]),
          "r"(b[0]), "r"(b[1]));
}

__global__ void __launch_bounds__(256, 2) gemm_tf32_kernel(float* __restrict__ C, int n) {
    int bx = blockIdx.x, by = blockIdx.y;
    if (bx > by) return;

    __shared__ uint32_t As[128 * SAK];   // rows of A tile, [row][k32chunk]
    __shared__ uint32_t Bs[128 * SAK];   // rows of B tile (cols of C)

    int tid  = threadIdx.x;
    int lane = tid & 31, wid = tid >> 5;
    int g    = lane >> 2, tig = lane & 3;     // groupID, threadID_in_group
    int wm   = wid & 3,  wn  = wid >> 2;     // warp grid 4x2

    const float4* H4 = (const float4*)g_h2;

    float acc[2][8][4];
#pragma unroll
    for (int mf = 0; mf < 2; mf++)
#pragma unroll
        for (int nf = 0; nf < 8; nf++)
#pragma unroll
            for (int i = 0; i < 4; i++) acc[mf][nf][i] = 0.0f;

#pragma unroll
    for (int kc = 0; kc < 2; kc++) {
        // Load chunk: 128 rows x 32 k for both tiles; relu + cvt to tf32.
#pragma unroll
        for (int i = 0; i < 4; i++) {
            int idx = i * 256 + tid;
            int row = idx >> 3, kq = idx & 7;
            float4 va = H4[(size_t)(by * 128 + row) * 16 + kc * 8 + kq];
            uint4 ta;
            ta.x = f2tf32(fmaxf(va.x, 0.f)); ta.y = f2tf32(fmaxf(va.y, 0.f));
            ta.z = f2tf32(fmaxf(va.z, 0.f)); ta.w = f2tf32(fmaxf(va.w, 0.f));
            *(uint4*)&As[row * SAK + kq * 4] = ta;
            float4 vb = H4[(size_t)(bx * 128 + row) * 16 + kc * 8 + kq];
            uint4 tb;
            tb.x = f2tf32(fmaxf(vb.x, 0.f)); tb.y = f2tf32(fmaxf(vb.y, 0.f));
            tb.z = f2tf32(fmaxf(vb.z, 0.f)); tb.w = f2tf32(fmaxf(vb.w, 0.f));
            *(uint4*)&Bs[row * SAK + kq * 4] = tb;
        }
        __syncthreads();

#pragma unroll
        for (int ks = 0; ks < 4; ks++) {
            int k0 = ks * 8;
            uint32_t a[2][4], b[8][2];
#pragma unroll
            for (int mf = 0; mf < 2; mf++) {
                int r = wm * 32 + mf * 16 + g;
                a[mf][0] = As[r * SAK + k0 + tig];
                a[mf][1] = As[(r + 8) * SAK + k0 + tig];
                a[mf][2] = As[r * SAK + k0 + tig + 4];
                a[mf][3] = As[(r + 8) * SAK + k0 + tig + 4];
            }
#pragma unroll
            for (int nf = 0; nf < 8; nf++) {
                int c = wn * 64 + nf * 8 + g;
                b[nf][0] = Bs[c * SAK + k0 + tig];
                b[nf][1] = Bs[c * SAK + k0 + tig + 4];
            }
#pragma unroll
            for (int mf = 0; mf < 2; mf++)
#pragma unroll
                for (int nf = 0; nf < 8; nf++)
                    mma_tf32(acc[mf][nf], a[mf], b[nf]);
        }
        __syncthreads();
    }

    // Direct (lower) tile: float2 stores.
#pragma unroll
    for (int mf = 0; mf < 2; mf++) {
        int row0 = by * 128 + wm * 32 + mf * 16 + g;
#pragma unroll
        for (int nf = 0; nf < 8; nf++) {
            int col = bx * 128 + wn * 64 + nf * 8 + 2 * tig;
            float2 lo = make_float2(acc[mf][nf][0], acc[mf][nf][1]);
            float2 hi = make_float2(acc[mf][nf][2], acc[mf][nf][3]);
            *(float2*)&C[(size_t)row0 * n + col] = lo;
            *(float2*)&C[(size_t)(row0 + 8) * n + col] = hi;
        }
    }
    // Mirror (upper) tile from registers.
    if (bx != by) {
#pragma unroll
        for (int mf = 0; mf < 2; mf++) {
            int row0 = by * 128 + wm * 32 + mf * 16 + g;
#pragma unroll
            for (int nf = 0; nf < 8; nf++) {
                int col = bx * 128 + wn * 64 + nf * 8 + 2 * tig;
                C[(size_t)col * n + row0]           = acc[mf][nf][0];
                C[(size_t)(col + 1) * n + row0]     = acc[mf][nf][1];
                C[(size_t)col * n + row0 + 8]       = acc[mf][nf][2];
                C[(size_t)(col + 1) * n + row0 + 8] = acc[mf][nf][3];
            }
        }
    }
}

// ---------------- Launcher (kernel launches ONLY) ----------------
extern "C" void kernel_launch(void* const* d_in, const int* in_sizes, int n_in,
                              void* d_out, int out_size) {
    const float* z  = (const float*)d_in[0];
    const void*  ei = d_in[1];              // int32 or int64 — probed on device
    const float* W  = (const float*)d_in[2];
    const float* b  = (const float*)d_in[3];
    float* out = (float*)d_out;

    int n = in_sizes[0] / DD;        // 16384
    int E = in_sizes[1] / 2;         // 524288

    detect_init_kernel<<<1, 32>>>();
    detect_kernel<<<(E + 255) / 256, 256>>>((const unsigned*)ei, E);

    linear_kernel<<<n * DD / 256, 256>>>(z, W);
    deg_init_kernel<<<(n + 255) / 256, 256>>>();
    deg_count_kernel<<<(E + 255) / 256, 256>>>(ei, E);
    dinv_kernel<<<(n + 255) / 256, 256>>>();
    init_out_kernel<<<n * DD / 256, 256>>>(b);
    scatter_kernel<<<(E * 16 + 255) / 256, 256>>>(ei, E);

    dim3 grid(n / 128, n / 128);
    gemm_tf32_kernel<<<grid, 256>>>(out, n);
}

// round 5
// speedup vs baseline: 2.7040x; 1.1201x over previous
#include <cuda_runtime.h>
#include <cuda_bf16.h>
#include <math.h>
#include <stdint.h>

#define NN 16384
#define DD 64

// Scratch (static __device__ — allocation is forbidden).
__device__ __align__(16) float g_h1[NN * DD];    // z @ W
__device__ __align__(16) float g_h2[NN * DD];    // GCN output (pre-relu)
__device__ float g_deg[NN];
__device__ float g_dinv[NN];
__device__ int   g_is64;                         // edge_index dtype flag

// ---------------- fused init: dtype flag + deg self-loops ----------------
__global__ void fused_init_kernel() {
    int i = blockIdx.x * 256 + threadIdx.x;
    if (i == 0) g_is64 = 1;
    if (i < NN) g_deg[i] = 1.0f;
}
// If ALL high u32 words of the first 2E words are zero -> int64 ids.
__global__ void detect_kernel(const unsigned* __restrict__ ei32, int E) {
    int i = blockIdx.x * 256 + threadIdx.x;      // over E pairs
    if (i < E && ei32[2 * i + 1] != 0u) g_is64 = 0;
}
__device__ __forceinline__ int edge_get(const void* ei, int is64, size_t idx) {
    if (is64) return (int)((const long long*)ei)[idx];
    return ((const int*)ei)[idx];
}

// ---------------- deg count over cols ----------------
__global__ void deg_count_kernel(const void* __restrict__ ei, int E) {
    int e = blockIdx.x * 256 + threadIdx.x;
    if (e >= E) return;
    int c = edge_get(ei, g_is64, (size_t)E + e);
    if ((unsigned)c < NN) atomicAdd(&g_deg[c], 1.0f);
}
// ---------------- dinv = 1/sqrt(deg) ----------------
__global__ void dinv_kernel() {
    int i = blockIdx.x * 256 + threadIdx.x;
    if (i < NN) g_dinv[i] = 1.0f / sqrtf(g_deg[i]);
}

// ---------------- fused: h1 = z@W ; h2 = h1*dinv^2 + b ----------------
__global__ void linear_fused_kernel(const float* __restrict__ z,
                                    const float* __restrict__ W,
                                    const float* __restrict__ b) {
    __shared__ float Ws[DD * DD];
    __shared__ float zs[4 * DD];
    int tid = threadIdx.x;                 // 256 threads
    int j = tid & 63;
    int rl = tid >> 6;
    for (int i = tid; i < DD * DD; i += 256) Ws[i] = W[i];
    size_t gi = (size_t)blockIdx.x * 256 + tid;
    zs[tid] = z[gi];
    __syncthreads();
    float s = 0.0f;
#pragma unroll
    for (int k = 0; k < DD; k++) s = fmaf(zs[rl * DD + k], Ws[k * DD + j], s);
    int node = (int)(gi >> 6);
    float di = g_dinv[node];
    g_h1[gi] = s;
    g_h2[gi] = s * di * di + b[j];
}

// ---------------- edge scatter: h2[col] += h1[row]*norm (vector RED) ----------------
__global__ void scatter_kernel(const void* __restrict__ ei, int E) {
    int t = blockIdx.x * 256 + threadIdx.x;  // over E*16
    int e = t >> 4;
    int q = t & 15;
    if (e >= E) return;
    int is64 = g_is64;
    int r = edge_get(ei, is64, (size_t)e);
    int c = edge_get(ei, is64, (size_t)E + e);
    if ((unsigned)r >= NN || (unsigned)c >= NN) return;
    float norm = g_dinv[r] * g_dinv[c];
    const float4 v = *(const float4*)&g_h1[((size_t)r << 6) + q * 4];
    float* dst = &g_h2[((size_t)c << 6) + q * 4];
    asm volatile("red.global.add.v4.f32 [%0], {%1,%2,%3,%4};"
                 :: "l"(dst), "f"(v.x * norm), "f"(v.y * norm),
                    "f"(v.z * norm), "f"(v.w * norm)
                 : "memory");
}

// ---------------- A = relu(h2) @ relu(h2)^T via mma.sync tf32 ----------------
// 128x128 block tile, full K=64 staged in one shot (dynamic smem 69.6KB,
// 2 CTAs/SM). 8 warps in 4(M)x2(N), warp tile 32x64. Natural [node][k]
// layout, stride 68 u32 -> conflict-free STS.128 and fragment LDS.
// Lower-triangular blocks only; mirror tile written from registers.
#define SK 68

__device__ __forceinline__ uint32_t f2tf32(float x) {
    uint32_t r;
    asm("cvt.rna.tf32.f32 %0, %1;" : "=r"(r) : "f"(x));
    return r;
}
__device__ __forceinline__ void mma_tf32(float* d, const uint32_t* a, const uint32_t* b) {
    asm("mma.sync.aligned.m16n8k8.row.col.f32.tf32.tf32.f32 "
        "{%0,%1,%2,%3}, {%4,%5,%6,%7}, {%8,%9}, {%0,%1,%2,%3};"
        : "+f"(d[0]), "+f"(d[1]), "+f"(d[2]), "+f"(d[3])
        : "r"(a[0]), "r"(a[1]), "r"(a[2]), "r"(a[3]),
          "r"(b[0]), "r"(b[1]));
}
__device__ __forceinline__ void stcs2(float* p, float x, float y) {
    asm volatile("st.global.cs.v2.f32 [%0], {%1,%2};" :: "l"(p), "f"(x), "f"(y) : "memory");
}
__device__ __forceinline__ void stcs1(float* p, float x) {
    asm volatile("st.global.cs.f32 [%0], %1;" :: "l"(p), "f"(x) : "memory");
}

__global__ void __launch_bounds__(256, 2) gemm_tf32_kernel(float* __restrict__ C, int n) {
    int bx = blockIdx.x, by = blockIdx.y;
    if (bx > by) return;

    extern __shared__ uint32_t sm[];
    uint32_t* As = sm;              // 128*SK
    uint32_t* Bs = sm + 128 * SK;   // 128*SK

    int tid  = threadIdx.x;
    int lane = tid & 31, wid = tid >> 5;
    int g    = lane >> 2, tig = lane & 3;     // groupID, threadID_in_group
    int wm   = wid & 3,  wn  = wid >> 2;      // warp grid 4x2

    const float4* H4 = (const float4*)g_h2;

    // Stage full 128x64 tiles for A and B (relu + tf32 convert).
#pragma unroll
    for (int i = 0; i < 8; i++) {
        int idx = i * 256 + tid;
        int row = idx >> 4, kq = idx & 15;
        float4 va = H4[(size_t)(by * 128 + row) * 16 + kq];
        uint4 ta;
        ta.x = f2tf32(fmaxf(va.x, 0.f)); ta.y = f2tf32(fmaxf(va.y, 0.f));
        ta.z = f2tf32(fmaxf(va.z, 0.f)); ta.w = f2tf32(fmaxf(va.w, 0.f));
        *(uint4*)&As[row * SK + kq * 4] = ta;
        float4 vb = H4[(size_t)(bx * 128 + row) * 16 + kq];
        uint4 tb;
        tb.x = f2tf32(fmaxf(vb.x, 0.f)); tb.y = f2tf32(fmaxf(vb.y, 0.f));
        tb.z = f2tf32(fmaxf(vb.z, 0.f)); tb.w = f2tf32(fmaxf(vb.w, 0.f));
        *(uint4*)&Bs[row * SK + kq * 4] = tb;
    }
    __syncthreads();

    float acc[2][8][4];
#pragma unroll
    for (int mf = 0; mf < 2; mf++)
#pragma unroll
        for (int nf = 0; nf < 8; nf++)
#pragma unroll
            for (int i = 0; i < 4; i++) acc[mf][nf][i] = 0.0f;

#pragma unroll
    for (int ks = 0; ks < 8; ks++) {
        int k0 = ks * 8;
        uint32_t a[2][4], b[8][2];
#pragma unroll
        for (int mf = 0; mf < 2; mf++) {
            int r = wm * 32 + mf * 16 + g;
            a[mf][0] = As[r * SK + k0 + tig];
            a[mf][1] = As[(r + 8) * SK + k0 + tig];
            a[mf][2] = As[r * SK + k0 + tig + 4];
            a[mf][3] = As[(r + 8) * SK + k0 + tig + 4];
        }
#pragma unroll
        for (int nf = 0; nf < 8; nf++) {
            int c = wn * 64 + nf * 8 + g;
            b[nf][0] = Bs[c * SK + k0 + tig];
            b[nf][1] = Bs[c * SK + k0 + tig + 4];
        }
#pragma unroll
        for (int mf = 0; mf < 2; mf++)
#pragma unroll
            for (int nf = 0; nf < 8; nf++)
                mma_tf32(acc[mf][nf], a[mf], b[nf]);
    }

    // Direct (lower) tile: streaming float2 stores.
#pragma unroll
    for (int mf = 0; mf < 2; mf++) {
        int row0 = by * 128 + wm * 32 + mf * 16 + g;
#pragma unroll
        for (int nf = 0; nf < 8; nf++) {
            int col = bx * 128 + wn * 64 + nf * 8 + 2 * tig;
            stcs2(&C[(size_t)row0 * n + col],       acc[mf][nf][0], acc[mf][nf][1]);
            stcs2(&C[(size_t)(row0 + 8) * n + col], acc[mf][nf][2], acc[mf][nf][3]);
        }
    }
    // Mirror (upper) tile from registers.
    if (bx != by) {
#pragma unroll
        for (int mf = 0; mf < 2; mf++) {
            int row0 = by * 128 + wm * 32 + mf * 16 + g;
#pragma unroll
            for (int nf = 0; nf < 8; nf++) {
                int col = bx * 128 + wn * 64 + nf * 8 + 2 * tig;
                stcs1(&C[(size_t)col * n + row0],           acc[mf][nf][0]);
                stcs1(&C[(size_t)(col + 1) * n + row0],     acc[mf][nf][1]);
                stcs1(&C[(size_t)col * n + row0 + 8],       acc[mf][nf][2]);
                stcs1(&C[(size_t)(col + 1) * n + row0 + 8], acc[mf][nf][3]);
            }
        }
    }
}

// ---------------- Launcher ----------------
extern "C" void kernel_launch(void* const* d_in, const int* in_sizes, int n_in,
                              void* d_out, int out_size) {
    const float* z  = (const float*)d_in[0];
    const void*  ei = d_in[1];              // int32 or int64 — probed on device
    const float* W  = (const float*)d_in[2];
    const float* b  = (const float*)d_in[3];
    float* out = (float*)d_out;

    int n = in_sizes[0] / DD;        // 16384
    int E = in_sizes[1] / 2;         // 524288

    fused_init_kernel<<<(n + 255) / 256, 256>>>();
    detect_kernel<<<(E + 255) / 256, 256>>>((const unsigned*)ei, E);
    deg_count_kernel<<<(E + 255) / 256, 256>>>(ei, E);
    dinv_kernel<<<(n + 255) / 256, 256>>>();
    linear_fused_kernel<<<n * DD / 256, 256>>>(z, W, b);
    scatter_kernel<<<(E * 16 + 255) / 256, 256>>>(ei, E);

    // A_hat = relu(h2) @ relu(h2)^T  (symmetric: lower-tri blocks + mirror)
    size_t smem_bytes = (size_t)(2 * 128 * SK) * sizeof(uint32_t);  // 69632
    cudaFuncSetAttribute(gemm_tf32_kernel,
                         cudaFuncAttributeMaxDynamicSharedMemorySize,
                         (int)smem_bytes);  // host-side attr, not a stream op
    dim3 grid(n / 128, n / 128);
    gemm_tf32_kernel<<<grid, 256, smem_bytes>>>(out, n);
}